// round 3
// baseline (speedup 1.0000x reference)
#include <cuda_runtime.h>
#include <cuda_fp16.h>
#include <cstdint>

#define THREADS 256
#define WPC 8          // windows per CTA
#define NTOK 49
#define DIMC 128
#define NHEAD 4

// shared memory layout (bytes)
#define OFF_WQ 0
#define OFF_WK 32768
#define OFF_WV 65536
#define OFF_WP 98304
#define OFF_X  131072   /* half 64x128, aliased with float sS 64x64 */
#define OFF_Q  147456
#define OFF_K  163840
#define OFF_V  180224
#define OFF_P  196608   /* half 64x64 */
#define OFF_O  204800
#define SMEM_BYTES 221184

// ---------------------------------------------------------------------------
// helpers
// ---------------------------------------------------------------------------
__device__ __forceinline__ uint32_t cvta_s(const void* p) {
  return (uint32_t)__cvta_generic_to_shared(p);
}

// XOR-swizzled half-tile indices (ld = 128 / 64 halves). Granule = 8 halves
// (16B); granule index XOR'd with row low bits -> conflict-free ldmatrix.
__device__ __forceinline__ uint32_t swz128(uint32_t r, uint32_t c) {
  return (r << 7) | ((((c >> 3) ^ (r & 7)) << 3) | (c & 7));
}
__device__ __forceinline__ uint32_t swz64(uint32_t r, uint32_t c) {
  return (r << 6) | ((((c >> 3) ^ (r & 7)) << 3) | (c & 7));
}
// fp32 score tile 64x64, granule = 4 floats (16B), swizzled
__device__ __forceinline__ uint32_t ssidx(uint32_t r, uint32_t c) {
  return (r << 6) | ((((c >> 2) ^ (r & 15)) << 2) | (c & 3));
}

__device__ __forceinline__ void ldsm_x4(uint32_t& r0, uint32_t& r1, uint32_t& r2,
                                        uint32_t& r3, uint32_t a) {
  asm volatile("ldmatrix.sync.aligned.m8n8.x4.shared.b16 {%0,%1,%2,%3}, [%4];"
               : "=r"(r0), "=r"(r1), "=r"(r2), "=r"(r3) : "r"(a));
}
__device__ __forceinline__ void ldsm_x2(uint32_t& r0, uint32_t& r1, uint32_t a) {
  asm volatile("ldmatrix.sync.aligned.m8n8.x2.shared.b16 {%0,%1}, [%2];"
               : "=r"(r0), "=r"(r1) : "r"(a));
}
__device__ __forceinline__ void ldsm_x2_t(uint32_t& r0, uint32_t& r1, uint32_t a) {
  asm volatile("ldmatrix.sync.aligned.m8n8.x2.trans.shared.b16 {%0,%1}, [%2];"
               : "=r"(r0), "=r"(r1) : "r"(a));
}
__device__ __forceinline__ void mma16816(float* c, uint32_t a0, uint32_t a1,
                                         uint32_t a2, uint32_t a3,
                                         uint32_t b0, uint32_t b1) {
  asm volatile(
      "mma.sync.aligned.m16n8k16.row.col.f32.f16.f16.f32 "
      "{%0,%1,%2,%3}, {%4,%5,%6,%7}, {%8,%9}, {%0,%1,%2,%3};"
      : "+f"(c[0]), "+f"(c[1]), "+f"(c[2]), "+f"(c[3])
      : "r"(a0), "r"(a1), "r"(a2), "r"(a3), "r"(b0), "r"(b1));
}

// ---------------------------------------------------------------------------
// loaders: fp32 global -> swizzled fp16 smem
// ---------------------------------------------------------------------------
__device__ void load_weight(const float* __restrict__ W, __half* dst) {
  const int tid = threadIdx.x;
  for (int g = tid; g < 2048; g += THREADS) {          // 128x128 / 8 granules
    int r = g >> 4, c = (g & 15) << 3;
    const float4* p = reinterpret_cast<const float4*>(W + r * 128 + c);
    float4 f0 = p[0], f1 = p[1];
    union { uint4 u; __half2 h[4]; } pk;
    pk.h[0] = __floats2half2_rn(f0.x, f0.y);
    pk.h[1] = __floats2half2_rn(f0.z, f0.w);
    pk.h[2] = __floats2half2_rn(f1.x, f1.y);
    pk.h[3] = __floats2half2_rn(f1.z, f1.w);
    *reinterpret_cast<uint4*>(dst + swz128(r, c)) = pk.u;
  }
}

__device__ void load_x(const float* __restrict__ xb, __half* dst) {
  const int tid = threadIdx.x;
  for (int g = tid; g < 1024; g += THREADS) {          // 64x128 / 8 granules
    int r = g >> 4, c = (g & 15) << 3;
    float4 f0 = make_float4(0.f, 0.f, 0.f, 0.f), f1 = f0;
    if (r < NTOK) {
      const float4* p = reinterpret_cast<const float4*>(xb + r * 128 + c);
      f0 = p[0]; f1 = p[1];
    }
    union { uint4 u; __half2 h[4]; } pk;
    pk.h[0] = __floats2half2_rn(f0.x, f0.y);
    pk.h[1] = __floats2half2_rn(f0.z, f0.w);
    pk.h[2] = __floats2half2_rn(f1.x, f1.y);
    pk.h[3] = __floats2half2_rn(f1.z, f1.w);
    *reinterpret_cast<uint4*>(dst + swz128(r, c)) = pk.u;
  }
}

// ---------------------------------------------------------------------------
// 64x128 = (64x128) @ (128x128)^T  projection GEMM
// ---------------------------------------------------------------------------
template <bool TO_GLOBAL>
__device__ void gemm_x128(const __half* A, const __half* B, __half* Csm,
                          float* __restrict__ Cg, const float* __restrict__ bias,
                          float scale) {
  const int tid = threadIdx.x, wid = tid >> 5, lane = tid & 31;
  const int wm = (wid >> 1) << 4;  // 0,16,32,48
  const int wn = (wid & 1) << 6;   // 0,64
  float acc[8][4];
#pragma unroll
  for (int t = 0; t < 8; t++)
#pragma unroll
    for (int i = 0; i < 4; i++) acc[t][i] = 0.f;
  const uint32_t aB = cvta_s(A), bB = cvta_s(B);
#pragma unroll
  for (int k = 0; k < 128; k += 16) {
    uint32_t a0, a1, a2, a3;
    ldsm_x4(a0, a1, a2, a3,
            aB + (swz128(wm + (lane & 15), k + ((lane >> 4) << 3)) << 1));
#pragma unroll
    for (int t = 0; t < 8; t++) {
      uint32_t b0, b1;
      ldsm_x2(b0, b1,
              bB + (swz128(wn + t * 8 + (lane & 7), k + (lane & 8)) << 1));
      mma16816(acc[t], a0, a1, a2, a3, b0, b1);
    }
  }
  const int r0 = wm + (lane >> 2);
#pragma unroll
  for (int t = 0; t < 8; t++) {
    int c0 = wn + t * 8 + ((lane & 3) << 1);
    float bz0 = bias[c0], bz1 = bias[c0 + 1];
    float v00 = (acc[t][0] + bz0) * scale, v01 = (acc[t][1] + bz1) * scale;
    float v10 = (acc[t][2] + bz0) * scale, v11 = (acc[t][3] + bz1) * scale;
    if (TO_GLOBAL) {
      if (r0 < NTOK) { Cg[r0 * 128 + c0] = v00; Cg[r0 * 128 + c0 + 1] = v01; }
      if (r0 + 8 < NTOK) {
        Cg[(r0 + 8) * 128 + c0] = v10; Cg[(r0 + 8) * 128 + c0 + 1] = v11;
      }
    } else {
      *reinterpret_cast<__half2*>(Csm + swz128(r0, c0)) = __floats2half2_rn(v00, v01);
      *reinterpret_cast<__half2*>(Csm + swz128(r0 + 8, c0)) = __floats2half2_rn(v10, v11);
    }
  }
}

// ---------------------------------------------------------------------------
// S = Q_h @ K_h^T (+ rel-pos bias + mask), fp32 scores into swizzled sS
// ---------------------------------------------------------------------------
__device__ void s_gemm(int h, const __half* Q, const __half* K, float* S,
                       const float* __restrict__ table,
                       const float* __restrict__ maskb) {
  const int tid = threadIdx.x, wid = tid >> 5, lane = tid & 31;
  const int wm = (wid >> 1) << 4;  // rows
  const int wn = (wid & 1) << 5;   // cols 0/32
  float acc[4][4];
#pragma unroll
  for (int t = 0; t < 4; t++)
#pragma unroll
    for (int i = 0; i < 4; i++) acc[t][i] = 0.f;
  const uint32_t qB = cvta_s(Q), kB = cvta_s(K);
#pragma unroll
  for (int s = 0; s < 2; s++) {
    int kb = h * 32 + s * 16;
    uint32_t a0, a1, a2, a3;
    ldsm_x4(a0, a1, a2, a3,
            qB + (swz128(wm + (lane & 15), kb + ((lane >> 4) << 3)) << 1));
#pragma unroll
    for (int t = 0; t < 4; t++) {
      uint32_t b0, b1;
      ldsm_x2(b0, b1,
              kB + (swz128(wn + t * 8 + (lane & 7), kb + (lane & 8)) << 1));
      mma16816(acc[t], a0, a1, a2, a3, b0, b1);
    }
  }
  const int r0 = wm + (lane >> 2);
#pragma unroll
  for (int t = 0; t < 4; t++) {
    int c0 = wn + t * 8 + ((lane & 3) << 1);
#pragma unroll
    for (int i = 0; i < 4; i++) {
      int r = r0 + (i >> 1) * 8;
      int c = c0 + (i & 1);
      float o;
      if (c >= NTOK) o = -1e30f;            // padded keys: masked out
      else if (r >= NTOK) o = 0.f;          // padded queries: don't care
      else {
        int dq = r / 7 - c / 7;
        int dw = r % 7 - c % 7;
        int bidx = (dq + 6) * 13 + (dw + 6);
        o = acc[t][i] + table[bidx * NHEAD + h] + maskb[r * NTOK + c];
      }
      S[ssidx(r, c)] = o;
    }
  }
}

// fp32 softmax over 64 cols (padded cols carry -1e30 -> exp == 0)
__device__ void softmax_p(const float* S, __half* P) {
  const int tid = threadIdx.x;
  const int r = tid >> 2, sub = tid & 3;   // 4 threads per row
  float vals[16];
  float m = -1e30f;
#pragma unroll
  for (int i = 0; i < 16; i++) {
    float v = S[ssidx(r, sub + (i << 2))];
    vals[i] = v;
    m = fmaxf(m, v);
  }
  m = fmaxf(m, __shfl_xor_sync(0xffffffffu, m, 1));
  m = fmaxf(m, __shfl_xor_sync(0xffffffffu, m, 2));
  float s = 0.f;
#pragma unroll
  for (int i = 0; i < 16; i++) {
    float e = __expf(vals[i] - m);
    vals[i] = e;
    s += e;
  }
  s += __shfl_xor_sync(0xffffffffu, s, 1);
  s += __shfl_xor_sync(0xffffffffu, s, 2);
  float inv = 1.f / s;
#pragma unroll
  for (int i = 0; i < 16; i++)
    P[swz64(r, sub + (i << 2))] = __float2half(vals[i] * inv);
}

// O_h = P @ V_h  (V accessed k-major via ldmatrix.trans)
__device__ void o_gemm(int h, const __half* P, const __half* V, __half* O) {
  const int tid = threadIdx.x, wid = tid >> 5, lane = tid & 31;
  const int wm = (wid >> 1) << 4;
  const int wn = (wid & 1) << 4;  // 16 cols per warp
  float acc[2][4];
#pragma unroll
  for (int t = 0; t < 2; t++)
#pragma unroll
    for (int i = 0; i < 4; i++) acc[t][i] = 0.f;
  const uint32_t pB = cvta_s(P), vB = cvta_s(V);
#pragma unroll
  for (int s = 0; s < 4; s++) {
    int kb = s * 16;
    uint32_t a0, a1, a2, a3;
    ldsm_x4(a0, a1, a2, a3,
            pB + (swz64(wm + (lane & 15), kb + ((lane >> 4) << 3)) << 1));
#pragma unroll
    for (int t = 0; t < 2; t++) {
      int d0 = h * 32 + wn + t * 8;
      uint32_t b0, b1;
      ldsm_x2_t(b0, b1, vB + (swz128(kb + (lane & 15), d0) << 1));
      mma16816(acc[t], a0, a1, a2, a3, b0, b1);
    }
  }
  const int r0 = wm + (lane >> 2);
#pragma unroll
  for (int t = 0; t < 2; t++) {
    int c0 = h * 32 + wn + t * 8 + ((lane & 3) << 1);
    *reinterpret_cast<__half2*>(O + swz128(r0, c0)) =
        __floats2half2_rn(acc[t][0], acc[t][1]);
    *reinterpret_cast<__half2*>(O + swz128(r0 + 8, c0)) =
        __floats2half2_rn(acc[t][2], acc[t][3]);
  }
}

// ---------------------------------------------------------------------------
// fused window-attention kernel: one CTA handles WPC windows
// ---------------------------------------------------------------------------
__global__ void __launch_bounds__(THREADS, 1)
winattn_kernel(const float* __restrict__ x1, const float* __restrict__ x2,
               const float* __restrict__ x3, const float* __restrict__ mask,
               const float* __restrict__ Wq, const float* __restrict__ bq,
               const float* __restrict__ Wk, const float* __restrict__ bk,
               const float* __restrict__ Wv, const float* __restrict__ bv,
               const float* __restrict__ table, const float* __restrict__ Wp,
               const float* __restrict__ bp, float* __restrict__ out,
               int B, int nW) {
  extern __shared__ unsigned char smem[];
  __half* sWq = reinterpret_cast<__half*>(smem + OFF_WQ);
  __half* sWk = reinterpret_cast<__half*>(smem + OFF_WK);
  __half* sWv = reinterpret_cast<__half*>(smem + OFF_WV);
  __half* sWp = reinterpret_cast<__half*>(smem + OFF_WP);
  __half* sX  = reinterpret_cast<__half*>(smem + OFF_X);
  float*  sS  = reinterpret_cast<float*>(smem + OFF_X);  // alias (post-V)
  __half* sQ  = reinterpret_cast<__half*>(smem + OFF_Q);
  __half* sK  = reinterpret_cast<__half*>(smem + OFF_K);
  __half* sV  = reinterpret_cast<__half*>(smem + OFF_V);
  __half* sP  = reinterpret_cast<__half*>(smem + OFF_P);
  __half* sO  = reinterpret_cast<__half*>(smem + OFF_O);

  // stage all four weight matrices once per CTA
  load_weight(Wq, sWq);
  load_weight(Wk, sWk);
  load_weight(Wv, sWv);
  load_weight(Wp, sWp);
  __syncthreads();

  const float scale = 0.17677669529663687f;  // 1/sqrt(32)

  for (int w = 0; w < WPC; ++w) {
    int b = blockIdx.x * WPC + w;
    if (b >= B) break;
    const size_t base = (size_t)b * NTOK * DIMC;

    load_x(x1 + base, sX);
    __syncthreads();
    gemm_x128<false>(sX, sWq, sQ, nullptr, bq, scale);
    __syncthreads();
    load_x(x2 + base, sX);
    __syncthreads();
    gemm_x128<false>(sX, sWk, sK, nullptr, bk, 1.0f);
    __syncthreads();
    load_x(x3 + base, sX);
    __syncthreads();
    gemm_x128<false>(sX, sWv, sV, nullptr, bv, 1.0f);
    __syncthreads();

    const float* maskb = mask + (size_t)(b % nW) * NTOK * NTOK;
#pragma unroll 1
    for (int h = 0; h < NHEAD; h++) {
      s_gemm(h, sQ, sK, sS, table, maskb);
      __syncthreads();
      softmax_p(sS, sP);
      __syncthreads();
      o_gemm(h, sP, sV, sO);
      __syncthreads();
    }

    gemm_x128<true>(sO, sWp, nullptr, out + base, bp, 1.0f);
    __syncthreads();
  }
}

// ---------------------------------------------------------------------------
extern "C" void kernel_launch(void* const* d_in, const int* in_sizes, int n_in,
                              void* d_out, int out_size) {
  (void)n_in; (void)out_size;
  const float* x1    = (const float*)d_in[0];
  const float* x2    = (const float*)d_in[1];
  const float* x3    = (const float*)d_in[2];
  const float* mask  = (const float*)d_in[3];
  const float* Wq    = (const float*)d_in[4];
  const float* bq    = (const float*)d_in[5];
  const float* Wk    = (const float*)d_in[6];
  const float* bk    = (const float*)d_in[7];
  const float* Wv    = (const float*)d_in[8];
  const float* bv    = (const float*)d_in[9];
  const float* table = (const float*)d_in[10];
  const float* Wp    = (const float*)d_in[11];
  const float* bp    = (const float*)d_in[12];
  float* out = (float*)d_out;

  int B  = in_sizes[0] / (NTOK * DIMC);
  int nW = in_sizes[3] / (NTOK * NTOK);

  cudaFuncSetAttribute(winattn_kernel,
                       cudaFuncAttributeMaxDynamicSharedMemorySize, SMEM_BYTES);

  int grid = (B + WPC - 1) / WPC;
  winattn_kernel<<<grid, THREADS, SMEM_BYTES>>>(
      x1, x2, x3, mask, Wq, bq, Wk, bk, Wv, bv, table, Wp, bp, out, B, nW);
}

// round 5
// speedup vs baseline: 1.2889x; 1.2889x over previous
#include <cuda_runtime.h>
#include <cuda_fp16.h>
#include <cstdint>

#define THREADS 256
#define WPC 4          // windows per CTA
#define NTOK 49
#define DIMC 128
#define NHEAD 4

// shared memory layout (bytes)
#define OFF_WQ 0
#define OFF_WK 32768
#define OFF_WV 65536
#define OFF_WP 98304
#define OFF_X1 131072   /* half 64x128; aliased with O */
#define OFF_X2 147456
#define OFF_X3 163840
#define OFF_Q  180224
#define OFF_K  196608
#define OFF_V  212992
#define SMEM_BYTES 229376

// ---------------------------------------------------------------------------
// helpers
// ---------------------------------------------------------------------------
__device__ __forceinline__ uint32_t cvta_s(const void* p) {
  return (uint32_t)__cvta_generic_to_shared(p);
}

// XOR-swizzled half-tile index (ld = 128 halves). Granule = 8 halves (16B).
__device__ __forceinline__ uint32_t swz128(uint32_t r, uint32_t c) {
  return (r << 7) | ((((c >> 3) ^ (r & 7)) << 3) | (c & 7));
}

__device__ __forceinline__ void ldsm_x4(uint32_t& r0, uint32_t& r1, uint32_t& r2,
                                        uint32_t& r3, uint32_t a) {
  asm volatile("ldmatrix.sync.aligned.m8n8.x4.shared.b16 {%0,%1,%2,%3}, [%4];"
               : "=r"(r0), "=r"(r1), "=r"(r2), "=r"(r3) : "r"(a));
}
__device__ __forceinline__ void ldsm_x2(uint32_t& r0, uint32_t& r1, uint32_t a) {
  asm volatile("ldmatrix.sync.aligned.m8n8.x2.shared.b16 {%0,%1}, [%2];"
               : "=r"(r0), "=r"(r1) : "r"(a));
}
__device__ __forceinline__ void ldsm_x2_t(uint32_t& r0, uint32_t& r1, uint32_t a) {
  asm volatile("ldmatrix.sync.aligned.m8n8.x2.trans.shared.b16 {%0,%1}, [%2];"
               : "=r"(r0), "=r"(r1) : "r"(a));
}
__device__ __forceinline__ void mma16816(float* c, uint32_t a0, uint32_t a1,
                                         uint32_t a2, uint32_t a3,
                                         uint32_t b0, uint32_t b1) {
  asm volatile(
      "mma.sync.aligned.m16n8k16.row.col.f32.f16.f16.f32 "
      "{%0,%1,%2,%3}, {%4,%5,%6,%7}, {%8,%9}, {%0,%1,%2,%3};"
      : "+f"(c[0]), "+f"(c[1]), "+f"(c[2]), "+f"(c[3])
      : "r"(a0), "r"(a1), "r"(a2), "r"(a3), "r"(b0), "r"(b1));
}
__device__ __forceinline__ uint32_t packh2(float a, float b) {
  __half2 h = __floats2half2_rn(a, b);
  return *reinterpret_cast<uint32_t*>(&h);
}

// ---------------------------------------------------------------------------
// loaders: fp32 global -> swizzled fp16 smem
// ---------------------------------------------------------------------------
__device__ void load_weight(const float* __restrict__ W, __half* dst) {
  const int tid = threadIdx.x;
  for (int g = tid; g < 2048; g += THREADS) {          // 128x128 / 8 granules
    int r = g >> 4, c = (g & 15) << 3;
    const float4* p = reinterpret_cast<const float4*>(W + r * 128 + c);
    float4 f0 = p[0], f1 = p[1];
    union { uint4 u; __half2 h[4]; } pk;
    pk.h[0] = __floats2half2_rn(f0.x, f0.y);
    pk.h[1] = __floats2half2_rn(f0.z, f0.w);
    pk.h[2] = __floats2half2_rn(f1.x, f1.y);
    pk.h[3] = __floats2half2_rn(f1.z, f1.w);
    *reinterpret_cast<uint4*>(dst + swz128(r, c)) = pk.u;
  }
}

__device__ void load_x(const float* __restrict__ xb, __half* dst) {
  const int tid = threadIdx.x;
  for (int g = tid; g < 1024; g += THREADS) {          // 64x128 / 8 granules
    int r = g >> 4, c = (g & 15) << 3;
    float4 f0 = make_float4(0.f, 0.f, 0.f, 0.f), f1 = f0;
    if (r < NTOK) {
      const float4* p = reinterpret_cast<const float4*>(xb + r * 128 + c);
      f0 = p[0]; f1 = p[1];
    }
    union { uint4 u; __half2 h[4]; } pk;
    pk.h[0] = __floats2half2_rn(f0.x, f0.y);
    pk.h[1] = __floats2half2_rn(f0.z, f0.w);
    pk.h[2] = __floats2half2_rn(f1.x, f1.y);
    pk.h[3] = __floats2half2_rn(f1.z, f1.w);
    *reinterpret_cast<uint4*>(dst + swz128(r, c)) = pk.u;
  }
}

// ---------------------------------------------------------------------------
// 64x128 = (64x128) @ (128x128)^T  projection GEMM (8 warps, 4x2 tiling)
// ---------------------------------------------------------------------------
template <bool TO_GLOBAL>
__device__ void gemm_x128(const __half* A, const __half* B, __half* Csm,
                          float* __restrict__ Cg, const float* __restrict__ bias,
                          float scale) {
  const int tid = threadIdx.x, wid = tid >> 5, lane = tid & 31;
  const int wm = (wid >> 1) << 4;  // 0,16,32,48
  const int wn = (wid & 1) << 6;   // 0,64
  float acc[8][4];
#pragma unroll
  for (int t = 0; t < 8; t++)
#pragma unroll
    for (int i = 0; i < 4; i++) acc[t][i] = 0.f;
  const uint32_t aB = cvta_s(A), bB = cvta_s(B);
#pragma unroll
  for (int k = 0; k < 128; k += 16) {
    uint32_t a0, a1, a2, a3;
    ldsm_x4(a0, a1, a2, a3,
            aB + (swz128(wm + (lane & 15), k + ((lane >> 4) << 3)) << 1));
#pragma unroll
    for (int t = 0; t < 8; t++) {
      uint32_t b0, b1;
      ldsm_x2(b0, b1,
              bB + (swz128(wn + t * 8 + (lane & 7), k + (lane & 8)) << 1));
      mma16816(acc[t], a0, a1, a2, a3, b0, b1);
    }
  }
  const int r0 = wm + (lane >> 2);
#pragma unroll
  for (int t = 0; t < 8; t++) {
    int c0 = wn + t * 8 + ((lane & 3) << 1);
    float bz0 = bias[c0], bz1 = bias[c0 + 1];
    float v00 = (acc[t][0] + bz0) * scale, v01 = (acc[t][1] + bz1) * scale;
    float v10 = (acc[t][2] + bz0) * scale, v11 = (acc[t][3] + bz1) * scale;
    if (TO_GLOBAL) {
      if (r0 < NTOK) { Cg[r0 * 128 + c0] = v00; Cg[r0 * 128 + c0 + 1] = v01; }
      if (r0 + 8 < NTOK) {
        Cg[(r0 + 8) * 128 + c0] = v10; Cg[(r0 + 8) * 128 + c0 + 1] = v11;
      }
    } else {
      *reinterpret_cast<__half2*>(Csm + swz128(r0, c0)) = __floats2half2_rn(v00, v01);
      *reinterpret_cast<__half2*>(Csm + swz128(r0 + 8, c0)) = __floats2half2_rn(v10, v11);
    }
  }
}

// ---------------------------------------------------------------------------
// Per-warp attention: 2 warps per head, S & softmax fully register-resident.
// Warp computes 32 query rows x 64 keys, then O-slice 32x32 into smem O.
// ---------------------------------------------------------------------------
__device__ void attn_warp(const __half* Q, const __half* K, const __half* V,
                          __half* O, const float* __restrict__ table,
                          const float* __restrict__ maskb) {
  const int tid = threadIdx.x, wid = tid >> 5, lane = tid & 31;
  const int h = wid >> 1;            // head 0..3
  const int mbase = (wid & 1) << 5;  // query rows 0 or 32
  const uint32_t qB = cvta_s(Q), kB = cvta_s(K), vB = cvta_s(V);

  float acc[2][8][4];                // [mtile][ntile][frag]: S scores
#pragma unroll
  for (int mi = 0; mi < 2; mi++)
#pragma unroll
    for (int t = 0; t < 8; t++)
#pragma unroll
      for (int i = 0; i < 4; i++) acc[mi][t][i] = 0.f;

  // ---- S = Q_h @ K_h^T ----
#pragma unroll
  for (int s = 0; s < 2; s++) {
    int kb = h * 32 + s * 16;
    uint32_t a[2][4];
#pragma unroll
    for (int mi = 0; mi < 2; mi++)
      ldsm_x4(a[mi][0], a[mi][1], a[mi][2], a[mi][3],
              qB + (swz128(mbase + mi * 16 + (lane & 15),
                           kb + ((lane >> 4) << 3)) << 1));
#pragma unroll
    for (int t = 0; t < 8; t++) {
      uint32_t b0, b1;
      ldsm_x2(b0, b1, kB + (swz128(t * 8 + (lane & 7), kb + (lane & 8)) << 1));
      mma16816(acc[0][t], a[0][0], a[0][1], a[0][2], a[0][3], b0, b1);
      mma16816(acc[1][t], a[1][0], a[1][1], a[1][2], a[1][3], b0, b1);
    }
  }

  // ---- epilogue: +bias +mask, pad-mask, register softmax ----
  const int rl = lane >> 2, cl = (lane & 3) << 1;
  float rmax[2][2] = {{-1e30f, -1e30f}, {-1e30f, -1e30f}};
#pragma unroll
  for (int mi = 0; mi < 2; mi++) {
#pragma unroll
    for (int j = 0; j < 2; j++) {
      int r = mbase + mi * 16 + j * 8 + rl;
      int rq = r / 7, rw = r % 7;
#pragma unroll
      for (int t = 0; t < 8; t++) {
#pragma unroll
        for (int e = 0; e < 2; e++) {
          int c = t * 8 + cl + e;
          float v = acc[mi][t][j * 2 + e];
          if (c >= NTOK) {
            v = -1e30f;
          } else if (r < NTOK) {
            int bidx = (rq - c / 7 + 6) * 13 + (rw - c % 7 + 6);
            v += table[bidx * NHEAD + h] + maskb[r * NTOK + c];
          }
          acc[mi][t][j * 2 + e] = v;
          rmax[mi][j] = fmaxf(rmax[mi][j], v);
        }
      }
    }
  }
#pragma unroll
  for (int mi = 0; mi < 2; mi++)
#pragma unroll
    for (int j = 0; j < 2; j++) {
      float m = rmax[mi][j];
      m = fmaxf(m, __shfl_xor_sync(0xffffffffu, m, 1));
      m = fmaxf(m, __shfl_xor_sync(0xffffffffu, m, 2));
      rmax[mi][j] = m;
    }
  float inv[2][2];
#pragma unroll
  for (int mi = 0; mi < 2; mi++)
#pragma unroll
    for (int j = 0; j < 2; j++) {
      float s = 0.f;
#pragma unroll
      for (int t = 0; t < 8; t++)
#pragma unroll
        for (int e = 0; e < 2; e++) {
          float ex = __expf(acc[mi][t][j * 2 + e] - rmax[mi][j]);
          acc[mi][t][j * 2 + e] = ex;
          s += ex;
        }
      s += __shfl_xor_sync(0xffffffffu, s, 1);
      s += __shfl_xor_sync(0xffffffffu, s, 2);
      inv[mi][j] = 1.f / s;
    }

  // ---- O_h(32x32) = P @ V_h ; P fragments built in registers ----
  float oacc[2][4][4];
#pragma unroll
  for (int mi = 0; mi < 2; mi++)
#pragma unroll
    for (int t = 0; t < 4; t++)
#pragma unroll
      for (int i = 0; i < 4; i++) oacc[mi][t][i] = 0.f;

#pragma unroll
  for (int jk = 0; jk < 4; jk++) {   // key chunks of 16
    uint32_t aP[2][4];
#pragma unroll
    for (int mi = 0; mi < 2; mi++) {
      aP[mi][0] = packh2(acc[mi][2 * jk][0] * inv[mi][0],
                         acc[mi][2 * jk][1] * inv[mi][0]);
      aP[mi][1] = packh2(acc[mi][2 * jk][2] * inv[mi][1],
                         acc[mi][2 * jk][3] * inv[mi][1]);
      aP[mi][2] = packh2(acc[mi][2 * jk + 1][0] * inv[mi][0],
                         acc[mi][2 * jk + 1][1] * inv[mi][0]);
      aP[mi][3] = packh2(acc[mi][2 * jk + 1][2] * inv[mi][1],
                         acc[mi][2 * jk + 1][3] * inv[mi][1]);
    }
#pragma unroll
    for (int t = 0; t < 4; t++) {
      int d0 = h * 32 + t * 8;
      uint32_t b0, b1;
      ldsm_x2_t(b0, b1, vB + (swz128(jk * 16 + (lane & 15), d0) << 1));
      mma16816(oacc[0][t], aP[0][0], aP[0][1], aP[0][2], aP[0][3], b0, b1);
      mma16816(oacc[1][t], aP[1][0], aP[1][1], aP[1][2], aP[1][3], b0, b1);
    }
  }

  // ---- store O slice (fp16 swizzled) ----
#pragma unroll
  for (int mi = 0; mi < 2; mi++) {
    int r = mbase + mi * 16 + rl;
#pragma unroll
    for (int t = 0; t < 4; t++) {
      int c0 = h * 32 + t * 8 + cl;
      *reinterpret_cast<__half2*>(O + swz128(r, c0)) =
          __floats2half2_rn(oacc[mi][t][0], oacc[mi][t][1]);
      *reinterpret_cast<__half2*>(O + swz128(r + 8, c0)) =
          __floats2half2_rn(oacc[mi][t][2], oacc[mi][t][3]);
    }
  }
}

// ---------------------------------------------------------------------------
// fused window-attention kernel: one CTA handles WPC windows
// ---------------------------------------------------------------------------
__global__ void __launch_bounds__(THREADS, 1)
winattn_kernel(const float* __restrict__ x1, const float* __restrict__ x2,
               const float* __restrict__ x3, const float* __restrict__ mask,
               const float* __restrict__ Wq, const float* __restrict__ bq,
               const float* __restrict__ Wk, const float* __restrict__ bk,
               const float* __restrict__ Wv, const float* __restrict__ bv,
               const float* __restrict__ table, const float* __restrict__ Wp,
               const float* __restrict__ bp, float* __restrict__ out,
               int B, int nW) {
  extern __shared__ unsigned char smem[];
  __half* sWq = reinterpret_cast<__half*>(smem + OFF_WQ);
  __half* sWk = reinterpret_cast<__half*>(smem + OFF_WK);
  __half* sWv = reinterpret_cast<__half*>(smem + OFF_WV);
  __half* sWp = reinterpret_cast<__half*>(smem + OFF_WP);
  __half* sX1 = reinterpret_cast<__half*>(smem + OFF_X1);
  __half* sX2 = reinterpret_cast<__half*>(smem + OFF_X2);
  __half* sX3 = reinterpret_cast<__half*>(smem + OFF_X3);
  __half* sQ  = reinterpret_cast<__half*>(smem + OFF_Q);
  __half* sK  = reinterpret_cast<__half*>(smem + OFF_K);
  __half* sV  = reinterpret_cast<__half*>(smem + OFF_V);
  __half* sO  = sX1;  // alias: X1 dead once Q is computed

  load_weight(Wq, sWq);
  load_weight(Wk, sWk);
  load_weight(Wv, sWv);
  load_weight(Wp, sWp);
  __syncthreads();

  const float scale = 0.17677669529663687f;  // 1/sqrt(32)

  for (int w = 0; w < WPC; ++w) {
    int b = blockIdx.x * WPC + w;
    if (b >= B) break;
    const size_t base = (size_t)b * NTOK * DIMC;

    // all three inputs at once: overlapped global latency, 1 sync
    load_x(x1 + base, sX1);
    load_x(x2 + base, sX2);
    load_x(x3 + base, sX3);
    __syncthreads();

    // three projection GEMMs back-to-back, no syncs between (independent)
    gemm_x128<false>(sX1, sWq, sQ, nullptr, bq, scale);
    gemm_x128<false>(sX2, sWk, sK, nullptr, bk, 1.0f);
    gemm_x128<false>(sX3, sWv, sV, nullptr, bv, 1.0f);
    __syncthreads();

    // all 4 heads in parallel (2 warps/head), softmax in registers
    const float* maskb = mask + (size_t)(b % nW) * NTOK * NTOK;
    attn_warp(sQ, sK, sV, sO, table, maskb);
    __syncthreads();

    // output projection straight to global
    gemm_x128<true>(sO, sWp, nullptr, out + base, bp, 1.0f);
    __syncthreads();  // protect sO (= sX1) before next window's load
  }
}

// ---------------------------------------------------------------------------
extern "C" void kernel_launch(void* const* d_in, const int* in_sizes, int n_in,
                              void* d_out, int out_size) {
  (void)n_in; (void)out_size;
  const float* x1    = (const float*)d_in[0];
  const float* x2    = (const float*)d_in[1];
  const float* x3    = (const float*)d_in[2];
  const float* mask  = (const float*)d_in[3];
  const float* Wq    = (const float*)d_in[4];
  const float* bq    = (const float*)d_in[5];
  const float* Wk    = (const float*)d_in[6];
  const float* bk    = (const float*)d_in[7];
  const float* Wv    = (const float*)d_in[8];
  const float* bv    = (const float*)d_in[9];
  const float* table = (const float*)d_in[10];
  const float* Wp    = (const float*)d_in[11];
  const float* bp    = (const float*)d_in[12];
  float* out = (float*)d_out;

  int B  = in_sizes[0] / (NTOK * DIMC);
  int nW = in_sizes[3] / (NTOK * NTOK);

  cudaFuncSetAttribute(winattn_kernel,
                       cudaFuncAttributeMaxDynamicSharedMemorySize, SMEM_BYTES);

  int grid = (B + WPC - 1) / WPC;
  winattn_kernel<<<grid, THREADS, SMEM_BYTES>>>(
      x1, x2, x3, mask, Wq, bq, Wk, bk, Wv, bv, table, Wp, bp, out, B, nW);
}

// round 6
// speedup vs baseline: 1.5995x; 1.2409x over previous
#include <cuda_runtime.h>
#include <cuda_fp16.h>
#include <cstdint>

#define THREADS 512
#define WPC 4          // windows per CTA
#define NTOK 49
#define DIMC 128
#define NHEAD 4

// shared memory layout (bytes)
#define OFF_WQ 0
#define OFF_WK 32768
#define OFF_WV 65536
#define OFF_WP 98304
#define OFF_X1 131072   /* half 64x128; aliased with O */
#define OFF_X2 147456
#define OFF_X3 163840
#define OFF_Q  180224
#define OFF_K  196608
#define OFF_V  212992
#define SMEM_BYTES 229376

// ---------------------------------------------------------------------------
// helpers
// ---------------------------------------------------------------------------
__device__ __forceinline__ uint32_t cvta_s(const void* p) {
  return (uint32_t)__cvta_generic_to_shared(p);
}

// XOR-swizzled half-tile index (ld = 128 halves). Granule = 8 halves (16B).
__device__ __forceinline__ uint32_t swz128(uint32_t r, uint32_t c) {
  return (r << 7) | ((((c >> 3) ^ (r & 7)) << 3) | (c & 7));
}

__device__ __forceinline__ void ldsm_x4(uint32_t& r0, uint32_t& r1, uint32_t& r2,
                                        uint32_t& r3, uint32_t a) {
  asm volatile("ldmatrix.sync.aligned.m8n8.x4.shared.b16 {%0,%1,%2,%3}, [%4];"
               : "=r"(r0), "=r"(r1), "=r"(r2), "=r"(r3) : "r"(a));
}
__device__ __forceinline__ void ldsm_x4_t(uint32_t& r0, uint32_t& r1, uint32_t& r2,
                                          uint32_t& r3, uint32_t a) {
  asm volatile("ldmatrix.sync.aligned.m8n8.x4.trans.shared.b16 {%0,%1,%2,%3}, [%4];"
               : "=r"(r0), "=r"(r1), "=r"(r2), "=r"(r3) : "r"(a));
}
__device__ __forceinline__ void mma16816(float* c, uint32_t a0, uint32_t a1,
                                         uint32_t a2, uint32_t a3,
                                         uint32_t b0, uint32_t b1) {
  asm volatile(
      "mma.sync.aligned.m16n8k16.row.col.f32.f16.f16.f32 "
      "{%0,%1,%2,%3}, {%4,%5,%6,%7}, {%8,%9}, {%0,%1,%2,%3};"
      : "+f"(c[0]), "+f"(c[1]), "+f"(c[2]), "+f"(c[3])
      : "r"(a0), "r"(a1), "r"(a2), "r"(a3), "r"(b0), "r"(b1));
}
__device__ __forceinline__ uint32_t packh2(float a, float b) {
  __half2 h = __floats2half2_rn(a, b);
  return *reinterpret_cast<uint32_t*>(&h);
}

// ---------------------------------------------------------------------------
// loaders: fp32 global -> swizzled fp16 smem
// ---------------------------------------------------------------------------
__device__ void load_weight(const float* __restrict__ W, __half* dst) {
  const int tid = threadIdx.x;
  for (int g = tid; g < 2048; g += THREADS) {          // 128x128 / 8 granules
    int r = g >> 4, c = (g & 15) << 3;
    const float4* p = reinterpret_cast<const float4*>(W + r * 128 + c);
    float4 f0 = p[0], f1 = p[1];
    union { uint4 u; __half2 h[4]; } pk;
    pk.h[0] = __floats2half2_rn(f0.x, f0.y);
    pk.h[1] = __floats2half2_rn(f0.z, f0.w);
    pk.h[2] = __floats2half2_rn(f1.x, f1.y);
    pk.h[3] = __floats2half2_rn(f1.z, f1.w);
    *reinterpret_cast<uint4*>(dst + swz128(r, c)) = pk.u;
  }
}

__device__ void load_x(const float* __restrict__ xb, __half* dst) {
  const int tid = threadIdx.x;
  for (int g = tid; g < 1024; g += THREADS) {          // 64x128 / 8 granules
    int r = g >> 4, c = (g & 15) << 3;
    float4 f0 = make_float4(0.f, 0.f, 0.f, 0.f), f1 = f0;
    if (r < NTOK) {
      const float4* p = reinterpret_cast<const float4*>(xb + r * 128 + c);
      f0 = p[0]; f1 = p[1];
    }
    union { uint4 u; __half2 h[4]; } pk;
    pk.h[0] = __floats2half2_rn(f0.x, f0.y);
    pk.h[1] = __floats2half2_rn(f0.z, f0.w);
    pk.h[2] = __floats2half2_rn(f1.x, f1.y);
    pk.h[3] = __floats2half2_rn(f1.z, f1.w);
    *reinterpret_cast<uint4*>(dst + swz128(r, c)) = pk.u;
  }
}

// ---------------------------------------------------------------------------
// 64x128 = (64x128) @ (128x128)^T  projection GEMM (16 warps, 4x4 tiling)
// each warp: 16 rows x 32 cols
// ---------------------------------------------------------------------------
template <bool TO_GLOBAL>
__device__ void gemm_x128(const __half* A, const __half* B, __half* Csm,
                          float* __restrict__ Cg, const float* __restrict__ bias,
                          float scale) {
  const int tid = threadIdx.x, wid = tid >> 5, lane = tid & 31;
  const int wm = (wid >> 2) << 4;  // 0,16,32,48
  const int wn = (wid & 3) << 5;   // 0,32,64,96
  float acc[4][4];
#pragma unroll
  for (int t = 0; t < 4; t++)
#pragma unroll
    for (int i = 0; i < 4; i++) acc[t][i] = 0.f;
  const uint32_t aB = cvta_s(A), bB = cvta_s(B);
#pragma unroll
  for (int k = 0; k < 128; k += 16) {
    uint32_t a0, a1, a2, a3;
    ldsm_x4(a0, a1, a2, a3,
            aB + (swz128(wm + (lane & 15), k + ((lane >> 4) << 3)) << 1));
#pragma unroll
    for (int tt = 0; tt < 2; tt++) {  // two n-tiles per x4 load
      uint32_t b0, b1, b2, b3;
      ldsm_x4(b0, b1, b2, b3,
              bB + (swz128(wn + tt * 16 + ((lane >> 4) << 3) + (lane & 7),
                           k + (lane & 8)) << 1));
      mma16816(acc[2 * tt], a0, a1, a2, a3, b0, b1);
      mma16816(acc[2 * tt + 1], a0, a1, a2, a3, b2, b3);
    }
  }
  const int r0 = wm + (lane >> 2);
#pragma unroll
  for (int t = 0; t < 4; t++) {
    int c0 = wn + t * 8 + ((lane & 3) << 1);
    float bz0 = bias[c0], bz1 = bias[c0 + 1];
    float v00 = (acc[t][0] + bz0) * scale, v01 = (acc[t][1] + bz1) * scale;
    float v10 = (acc[t][2] + bz0) * scale, v11 = (acc[t][3] + bz1) * scale;
    if (TO_GLOBAL) {
      if (r0 < NTOK) { Cg[r0 * 128 + c0] = v00; Cg[r0 * 128 + c0 + 1] = v01; }
      if (r0 + 8 < NTOK) {
        Cg[(r0 + 8) * 128 + c0] = v10; Cg[(r0 + 8) * 128 + c0 + 1] = v11;
      }
    } else {
      *reinterpret_cast<__half2*>(Csm + swz128(r0, c0)) = __floats2half2_rn(v00, v01);
      *reinterpret_cast<__half2*>(Csm + swz128(r0 + 8, c0)) = __floats2half2_rn(v10, v11);
    }
  }
}

// ---------------------------------------------------------------------------
// Per-warp attention: 4 warps per head; S & softmax fully register-resident.
// Warp computes 16 query rows x 64 keys, then O-slice 16x32 into smem O.
// ---------------------------------------------------------------------------
__device__ void attn_warp(const __half* Q, const __half* K, const __half* V,
                          __half* O, const float* __restrict__ table,
                          const float* __restrict__ maskb) {
  const int tid = threadIdx.x, wid = tid >> 5, lane = tid & 31;
  const int h = wid >> 2;            // head 0..3
  const int mbase = (wid & 3) << 4;  // query rows 0,16,32,48
  const uint32_t qB = cvta_s(Q), kB = cvta_s(K), vB = cvta_s(V);

  float acc[8][4];                   // S scores: 16 rows x 64 keys
#pragma unroll
  for (int t = 0; t < 8; t++)
#pragma unroll
    for (int i = 0; i < 4; i++) acc[t][i] = 0.f;

  // ---- S = Q_h @ K_h^T ----
#pragma unroll
  for (int s = 0; s < 2; s++) {
    int kb = h * 32 + s * 16;
    uint32_t a0, a1, a2, a3;
    ldsm_x4(a0, a1, a2, a3,
            qB + (swz128(mbase + (lane & 15), kb + ((lane >> 4) << 3)) << 1));
#pragma unroll
    for (int tt = 0; tt < 4; tt++) {  // two key-tiles per x4 load
      uint32_t b0, b1, b2, b3;
      ldsm_x4(b0, b1, b2, b3,
              kB + (swz128(tt * 16 + ((lane >> 4) << 3) + (lane & 7),
                           kb + (lane & 8)) << 1));
      mma16816(acc[2 * tt], a0, a1, a2, a3, b0, b1);
      mma16816(acc[2 * tt + 1], a0, a1, a2, a3, b2, b3);
    }
  }

  // ---- epilogue: +bias +mask, pad-mask, register softmax ----
  const int rl = lane >> 2, cl = (lane & 3) << 1;
  float rmax[2] = {-1e30f, -1e30f};
#pragma unroll
  for (int j = 0; j < 2; j++) {
    int r = mbase + j * 8 + rl;
    int rq = r / 7, rw = r % 7;
#pragma unroll
    for (int t = 0; t < 8; t++) {
#pragma unroll
      for (int e = 0; e < 2; e++) {
        int c = t * 8 + cl + e;
        float v = acc[t][j * 2 + e];
        if (c >= NTOK) {
          v = -1e30f;
        } else if (r < NTOK) {
          int bidx = (rq - c / 7 + 6) * 13 + (rw - c % 7 + 6);
          v += table[bidx * NHEAD + h] + maskb[r * NTOK + c];
        }
        acc[t][j * 2 + e] = v;
        rmax[j] = fmaxf(rmax[j], v);
      }
    }
  }
  float inv[2];
#pragma unroll
  for (int j = 0; j < 2; j++) {
    float m = rmax[j];
    m = fmaxf(m, __shfl_xor_sync(0xffffffffu, m, 1));
    m = fmaxf(m, __shfl_xor_sync(0xffffffffu, m, 2));
    float s = 0.f;
#pragma unroll
    for (int t = 0; t < 8; t++)
#pragma unroll
      for (int e = 0; e < 2; e++) {
        float ex = __expf(acc[t][j * 2 + e] - m);
        acc[t][j * 2 + e] = ex;
        s += ex;
      }
    s += __shfl_xor_sync(0xffffffffu, s, 1);
    s += __shfl_xor_sync(0xffffffffu, s, 2);
    inv[j] = 1.f / s;
  }

  // ---- O_h(16x32) = P @ V_h ; P fragments built in registers ----
  float oacc[4][4];
#pragma unroll
  for (int t = 0; t < 4; t++)
#pragma unroll
    for (int i = 0; i < 4; i++) oacc[t][i] = 0.f;

#pragma unroll
  for (int jk = 0; jk < 4; jk++) {   // key chunks of 16
    uint32_t aP[4];
    aP[0] = packh2(acc[2 * jk][0] * inv[0], acc[2 * jk][1] * inv[0]);
    aP[1] = packh2(acc[2 * jk][2] * inv[1], acc[2 * jk][3] * inv[1]);
    aP[2] = packh2(acc[2 * jk + 1][0] * inv[0], acc[2 * jk + 1][1] * inv[0]);
    aP[3] = packh2(acc[2 * jk + 1][2] * inv[1], acc[2 * jk + 1][3] * inv[1]);
#pragma unroll
    for (int tt = 0; tt < 2; tt++) {  // two d-tiles per x4 trans load
      int d0 = h * 32 + tt * 16 + ((lane >> 4) << 3);
      uint32_t b0, b1, b2, b3;
      ldsm_x4_t(b0, b1, b2, b3,
                vB + (swz128(jk * 16 + (lane & 15), d0) << 1));
      mma16816(oacc[2 * tt], aP[0], aP[1], aP[2], aP[3], b0, b1);
      mma16816(oacc[2 * tt + 1], aP[0], aP[1], aP[2], aP[3], b2, b3);
    }
  }

  // ---- store O slice (fp16 swizzled) ----
  const int r = mbase + rl;
#pragma unroll
  for (int t = 0; t < 4; t++) {
    int c0 = h * 32 + t * 8 + cl;
    *reinterpret_cast<__half2*>(O + swz128(r, c0)) =
        __floats2half2_rn(oacc[t][0], oacc[t][1]);
    *reinterpret_cast<__half2*>(O + swz128(r + 8, c0)) =
        __floats2half2_rn(oacc[t][2], oacc[t][3]);
  }
}

// ---------------------------------------------------------------------------
// fused window-attention kernel: one CTA handles WPC windows
// ---------------------------------------------------------------------------
__global__ void __launch_bounds__(THREADS, 1)
winattn_kernel(const float* __restrict__ x1, const float* __restrict__ x2,
               const float* __restrict__ x3, const float* __restrict__ mask,
               const float* __restrict__ Wq, const float* __restrict__ bq,
               const float* __restrict__ Wk, const float* __restrict__ bk,
               const float* __restrict__ Wv, const float* __restrict__ bv,
               const float* __restrict__ table, const float* __restrict__ Wp,
               const float* __restrict__ bp, float* __restrict__ out,
               int B, int nW) {
  extern __shared__ unsigned char smem[];
  __half* sWq = reinterpret_cast<__half*>(smem + OFF_WQ);
  __half* sWk = reinterpret_cast<__half*>(smem + OFF_WK);
  __half* sWv = reinterpret_cast<__half*>(smem + OFF_WV);
  __half* sWp = reinterpret_cast<__half*>(smem + OFF_WP);
  __half* sX1 = reinterpret_cast<__half*>(smem + OFF_X1);
  __half* sX2 = reinterpret_cast<__half*>(smem + OFF_X2);
  __half* sX3 = reinterpret_cast<__half*>(smem + OFF_X3);
  __half* sQ  = reinterpret_cast<__half*>(smem + OFF_Q);
  __half* sK  = reinterpret_cast<__half*>(smem + OFF_K);
  __half* sV  = reinterpret_cast<__half*>(smem + OFF_V);
  __half* sO  = sX1;  // alias: X1 dead once Q is computed

  load_weight(Wq, sWq);
  load_weight(Wk, sWk);
  load_weight(Wv, sWv);
  load_weight(Wp, sWp);
  __syncthreads();

  const float scale = 0.17677669529663687f;  // 1/sqrt(32)

  for (int w = 0; w < WPC; ++w) {
    int b = blockIdx.x * WPC + w;
    if (b >= B) break;
    const size_t base = (size_t)b * NTOK * DIMC;

    // all three inputs at once: overlapped global latency, 1 sync
    load_x(x1 + base, sX1);
    load_x(x2 + base, sX2);
    load_x(x3 + base, sX3);
    __syncthreads();

    // three projection GEMMs back-to-back, no syncs between (independent)
    gemm_x128<false>(sX1, sWq, sQ, nullptr, bq, scale);
    gemm_x128<false>(sX2, sWk, sK, nullptr, bk, 1.0f);
    gemm_x128<false>(sX3, sWv, sV, nullptr, bv, 1.0f);
    __syncthreads();

    // all 4 heads in parallel (4 warps/head), softmax in registers
    const float* maskb = mask + (size_t)(b % nW) * NTOK * NTOK;
    attn_warp(sQ, sK, sV, sO, table, maskb);
    __syncthreads();

    // output projection straight to global
    gemm_x128<true>(sO, sWp, nullptr, out + base, bp, 1.0f);
    __syncthreads();  // protect sO (= sX1) before next window's load
  }
}

// ---------------------------------------------------------------------------
extern "C" void kernel_launch(void* const* d_in, const int* in_sizes, int n_in,
                              void* d_out, int out_size) {
  (void)n_in; (void)out_size;
  const float* x1    = (const float*)d_in[0];
  const float* x2    = (const float*)d_in[1];
  const float* x3    = (const float*)d_in[2];
  const float* mask  = (const float*)d_in[3];
  const float* Wq    = (const float*)d_in[4];
  const float* bq    = (const float*)d_in[5];
  const float* Wk    = (const float*)d_in[6];
  const float* bk    = (const float*)d_in[7];
  const float* Wv    = (const float*)d_in[8];
  const float* bv    = (const float*)d_in[9];
  const float* table = (const float*)d_in[10];
  const float* Wp    = (const float*)d_in[11];
  const float* bp    = (const float*)d_in[12];
  float* out = (float*)d_out;

  int B  = in_sizes[0] / (NTOK * DIMC);
  int nW = in_sizes[3] / (NTOK * NTOK);

  cudaFuncSetAttribute(winattn_kernel,
                       cudaFuncAttributeMaxDynamicSharedMemorySize, SMEM_BYTES);

  int grid = (B + WPC - 1) / WPC;
  winattn_kernel<<<grid, THREADS, SMEM_BYTES>>>(
      x1, x2, x3, mask, Wq, bq, Wk, bk, Wv, bv, table, Wp, bp, out, B, nW);
}